// round 6
// baseline (speedup 1.0000x reference)
#include <cuda_runtime.h>
#include <math.h>

#define N_   131072
#define D_   64
#define K_   2048
#define RPB  128              // rows per block
#define XSS  132              // padded xs stride (floats)
#define TPB  256
#define GRID (N_ / RPB)       // 1024 blocks
#define NCG  16               // code groups of 128
#define MARG_I 2080           // int-dot margin: 2*1032 + slack (provable bound)
#define QTH  24               // per-thread queue capacity
#define BTW  2052             // bT word stride per dg (2048 + 4 pad)
#define BTWORDS (16 * BTW)    // 32832 words = 131328 B

typedef unsigned int u32;
typedef unsigned long long u64;

// Device scratch (no allocations allowed)
__device__ __align__(16) float g_en  [K_ * D_];    // normalized codebook fp32
__device__ __align__(16) float g_see [K_];         // sum(en^2) per code
__device__ __align__(16) u32   g_bqT [BTWORDS];    // int8 codebook, transposed [dg][code]
__device__ float g_part[GRID];

// ---- smem byte offsets ----
#define OFF_BT   0            // 131328  bT u32[16][2052]
#define OFF_AT   131328       // 8448    aT u32[16][132] (int8-packed x rows)
#define OFF_XS   139776       // 33792   xs fp32 [64][132]
#define OFF_SXX  173568       // 512
#define OFF_RMX  174080       // 512     int[128] global row max (int dot)
#define OFF_RB   174592       // 1024    u64[128] packed (valbits, code)
#define OFF_Q    175616       // 24576   queues, interleaved [i][tid]
#define DYNSMEM  200192

// ---------------- helpers ----------------
__device__ __forceinline__ u32 smem_u32(const void* p) {
    u32 a; asm("{ .reg .u64 t; cvta.to.shared.u64 t, %1; cvt.u32.u64 %0, t; }" : "=r"(a) : "l"(p));
    return a;
}
__device__ __forceinline__ void cp16(u32 dst, const void* src) {
    asm volatile("cp.async.cg.shared.global [%0], [%1], 16;" :: "r"(dst), "l"(src) : "memory");
}
__device__ __forceinline__ void cp_commit() { asm volatile("cp.async.commit_group;" ::: "memory"); }
__device__ __forceinline__ void cp_wait0() {
    asm volatile("cp.async.wait_group 0;" ::: "memory");
}
// exact fp32 rescore (identical formula/order to passing R2/R4/R5) + atomicMin key
__device__ __noinline__ void exact_rescore(const float* xs, const float* sxx,
                                           u64* rbest, int row, int code) {
    float dot = 0.f;
    const float* er = g_en + code * 64;
    #pragma unroll
    for (int d = 0; d < 64; d++) dot = fmaf(xs[d * XSS + row], er[d], dot);
    float val = fmaf(-2.0f, dot, sxx[row] + g_see[code]);
    u32 vb = __float_as_uint(val);
    vb = (vb & 0x80000000u) ? ~vb : (vb | 0x80000000u);
    u64 key = ((u64)vb << 32) | (u32)code;
    atomicMin(rbest + row, key);
}
__device__ __forceinline__ u32 pack4(float a, float b, float c, float d) {
    int i0 = __float2int_rn(a * 127.f) & 255;
    int i1 = __float2int_rn(b * 127.f) & 255;
    int i2 = __float2int_rn(c * 127.f) & 255;
    int i3 = __float2int_rn(d * 127.f) & 255;
    return (u32)(i0 | (i1 << 8) | (i2 << 16) | (i3 << 24));
}

// ---------------------------------------------------------------------------
// Kernel 1: normalize embeddings -> g_en, g_see, and g_bqT (int8 transposed).
// One warp per code row.
// ---------------------------------------------------------------------------
__global__ void vq_norm_emb(const float* __restrict__ emb) {
    int w    = (blockIdx.x * blockDim.x + threadIdx.x) >> 5;
    int lane = threadIdx.x & 31;
    if (w >= K_) return;
    float v0 = emb[w * 64 + lane];
    float v1 = emb[w * 64 + lane + 32];
    float s  = v0 * v0 + v1 * v1;
    #pragma unroll
    for (int o = 16; o > 0; o >>= 1) s += __shfl_xor_sync(0xffffffffu, s, o);
    float inv = 1.0f / fmaxf(sqrtf(s), 1e-12f);
    float e0 = v0 * inv, e1 = v1 * inv;
    g_en[w * 64 + lane]      = e0;
    g_en[w * 64 + lane + 32] = e1;
    float t = e0 * e0 + e1 * e1;   // see from ROUNDED values (matches reference)
    #pragma unroll
    for (int o = 16; o > 0; o >>= 1) t += __shfl_xor_sync(0xffffffffu, t, o);
    if (lane == 0) g_see[w] = t;
    // gather 4 consecutive dims to lane dg (dg = lane, valid lanes 0..15)
    int sl = (4 * lane) & 31;
    float a0 = __shfl_sync(0xffffffffu, e0, sl),     b0 = __shfl_sync(0xffffffffu, e1, sl);
    float a1 = __shfl_sync(0xffffffffu, e0, sl + 1), b1 = __shfl_sync(0xffffffffu, e1, sl + 1);
    float a2 = __shfl_sync(0xffffffffu, e0, sl + 2), b2 = __shfl_sync(0xffffffffu, e1, sl + 2);
    float a3 = __shfl_sync(0xffffffffu, e0, sl + 3), b3 = __shfl_sync(0xffffffffu, e1, sl + 3);
    if (lane < 16) {
        bool hi = lane >= 8;
        float q0 = hi ? b0 : a0, q1 = hi ? b1 : a1;
        float q2 = hi ? b2 : a2, q3 = hi ? b3 : a3;
        g_bqT[lane * BTW + w] = pack4(q0, q1, q2, q3);
    }
}

// ---------------------------------------------------------------------------
// Kernel 2: dp4a int8 screening (whole codebook in smem) + exact fp32 rescore.
// 256 threads; thread tile 8 rows (ty) x 8 codes strided 16 (tx) per group.
// ---------------------------------------------------------------------------
extern __shared__ char smem_[];

__global__ void __launch_bounds__(TPB, 1)
vq_main(const float* __restrict__ x, float* __restrict__ out, int out_size) {
    char* base = smem_;
    u32*   bT   = (u32*)  (base + OFF_BT);
    u32*   aT   = (u32*)  (base + OFF_AT);
    float* xs   = (float*)(base + OFF_XS);
    float* sxx  = (float*)(base + OFF_SXX);
    int*   rmxI = (int*)  (base + OFF_RMX);
    u64*   rbest= (u64*)  (base + OFF_RB);
    u32*   qbuf = (u32*)  (base + OFF_Q);   // entry i of thread t at [i*TPB + t]

    int tid = threadIdx.x;
    int tx  = tid & 15;            // code lane
    int ty  = tid >> 4;            // row group (8 rows)
    int rowbase = blockIdx.x * RPB;

    if (tid < RPB) { rbest[tid] = 0xFFFFFFFFFFFFFFFFull; rmxI[tid] = -(1 << 30); }

    // async copy of the whole int8 codebook (131328 B) into smem
    {
        u32 dst = smem_u32(bT);
        const char* src = (const char*)g_bqT;
        #pragma unroll
        for (int i = 0; i < 33; i++) {
            int idx = i * TPB + tid;
            if (idx < BTWORDS / 4) cp16(dst + (u32)idx * 16u, src + (size_t)idx * 16);
        }
        cp_commit();
    }

    // load x tile, transposed
    #pragma unroll
    for (int i = 0; i < 32; i++) {
        int e = i * TPB + tid;
        int r = e >> 6, d = e & 63;
        xs[d * XSS + r] = x[(rowbase + r) * 64 + d];
    }
    __syncthreads();

    // normalize rows; sxx; pack this row to int8 aT[dg][row]
    if (tid < RPB) {
        float s = 0.f;
        #pragma unroll
        for (int d = 0; d < 64; d++) { float v = xs[d * XSS + tid]; s += v * v; }
        float inv = 1.0f / fmaxf(sqrtf(s), 1e-12f);
        float s2 = 0.f;
        #pragma unroll
        for (int d = 0; d < 64; d++) {
            float v = xs[d * XSS + tid] * inv;
            xs[d * XSS + tid] = v;
            s2 += v * v;
        }
        sxx[tid] = s2;
        #pragma unroll
        for (int dg = 0; dg < 16; dg++) {
            aT[dg * 132 + tid] = pack4(xs[(4 * dg + 0) * XSS + tid],
                                       xs[(4 * dg + 1) * XSS + tid],
                                       xs[(4 * dg + 2) * XSS + tid],
                                       xs[(4 * dg + 3) * XSS + tid]);
        }
    }
    cp_wait0();
    __syncthreads();

    int runm[8];
    #pragma unroll
    for (int j = 0; j < 8; j++) runm[j] = -(1 << 30);
    int qn = 0;

    for (int cg = 0; cg < NCG; cg++) {
        int acc[8][8];
        #pragma unroll
        for (int j = 0; j < 8; j++)
            #pragma unroll
            for (int i = 0; i < 8; i++) acc[j][i] = 0;

        const u32* bb = bT + cg * 128 + tx;
        const u32* aa = aT + ty * 8;

        #pragma unroll 4
        for (int dg = 0; dg < 16; dg++) {
            uint4 A0 = *(const uint4*)(aa + dg * 132);
            uint4 A1 = *(const uint4*)(aa + dg * 132 + 4);
            u32 av[8] = {A0.x, A0.y, A0.z, A0.w, A1.x, A1.y, A1.z, A1.w};
            u32 bv[8];
            #pragma unroll
            for (int i = 0; i < 8; i++) bv[i] = bb[dg * BTW + i * 16];
            #pragma unroll
            for (int j = 0; j < 8; j++)
                #pragma unroll
                for (int i = 0; i < 8; i++)
                    acc[j][i] = __dp4a((int)av[j], (int)bv[i], acc[j][i]);
        }

        // group-max fast path per row
        #pragma unroll
        for (int j = 0; j < 8; j++) {
            int gm = max(max(max(acc[j][0], acc[j][1]), max(acc[j][2], acc[j][3])),
                         max(max(acc[j][4], acc[j][5]), max(acc[j][6], acc[j][7])));
            if (gm > runm[j] - MARG_I) {               // rare slow path
                int th = max(runm[j], gm) - MARG_I;
                #pragma unroll
                for (int i = 0; i < 8; i++) {
                    if (acc[j][i] > th) {
                        int code = cg * 128 + i * 16 + tx;
                        if (qn >= QTH) {               // purge stale entries
                            int w2 = 0;
                            for (int q = 0; q < qn; q++) {
                                u32 e = qbuf[q * TPB + tid];
                                int jj = (e >> 11) & 7;
                                int ev = (int)(e >> 16) - 32768;
                                if (ev + MARG_I >= runm[jj]) qbuf[w2++ * TPB + tid] = e;
                            }
                            qn = w2;
                        }
                        if (qn < QTH) {
                            qbuf[qn * TPB + tid] =
                                ((u32)(acc[j][i] + 32768) << 16) | ((u32)j << 11) | (u32)code;
                            qn++;
                        } else {
                            exact_rescore(xs, sxx, rbest, ty * 8 + j, code);
                        }
                    }
                }
            }
            runm[j] = max(runm[j], gm);
        }
    }

    // global per-row max (int) across threads
    #pragma unroll
    for (int j = 0; j < 8; j++) atomicMax(&rmxI[ty * 8 + j], runm[j]);
    __syncthreads();

    // refilter queue vs global row max; exact-rescore survivors
    for (int i = 0; i < qn; i++) {
        u32 e = qbuf[i * TPB + tid];
        int code = e & 2047;
        int j    = (e >> 11) & 7;
        int ev   = (int)(e >> 16) - 32768;
        if (ev + MARG_I >= rmxI[ty * 8 + j])
            exact_rescore(xs, sxx, rbest, ty * 8 + j, code);
    }
    __syncthreads();

    // ---- per-row final: quantized_st, idx, loss ----
    float lsum = 0.f;
    if (tid < RPB) {
        int bk = (int)(rbest[tid] & 2047u);
        float inv2 = 1.0f / fmaxf(sqrtf(g_see[bk]), 1e-12f);
        const float* erow = g_en + bk * 64;
        #pragma unroll
        for (int d = 0; d < 64; d++) {
            float xnv  = xs[d * XSS + tid];
            float qd   = erow[d] * inv2;
            float diff = qd - xnv;
            lsum += diff * diff;
            xs[d * XSS + tid] = xnv + diff;
        }
        if (out_size >= N_ * D_ + 1 + N_)
            out[N_ * D_ + 1 + rowbase + tid] = (float)bk;
    }
    __syncthreads();

    // coalesced store of quantized_st
    #pragma unroll
    for (int i = 0; i < 32; i++) {
        int e = i * TPB + tid;
        out[rowbase * 64 + e] = xs[(e & 63) * XSS + (e >> 6)];
    }

    // deterministic block loss reduction
    float* red = (float*)(base + OFF_SXX);   // sxx no longer needed
    if (tid < RPB) red[tid] = lsum;
    __syncthreads();
    for (int s = 64; s > 0; s >>= 1) {
        if (tid < s) red[tid] += red[tid + s];
        __syncthreads();
    }
    if (tid == 0) g_part[blockIdx.x] = red[0];
}

// ---------------------------------------------------------------------------
// Kernel 3: deterministic final loss reduction.
// loss = q_latent + 0.25*e_latent = 1.25 * mean((q - xn)^2)
// ---------------------------------------------------------------------------
__global__ void vq_final(float* __restrict__ out, int out_size) {
    __shared__ float sm[256];
    int tid = threadIdx.x;
    float s = g_part[tid] + g_part[tid + 256] + g_part[tid + 512] + g_part[tid + 768];
    sm[tid] = s;
    __syncthreads();
    for (int st = 128; st > 0; st >>= 1) {
        if (tid < st) sm[tid] += sm[tid + st];
        __syncthreads();
    }
    if (tid == 0 && out_size > N_ * D_)
        out[N_ * D_] = 1.25f * (sm[0] / (float)(N_ * D_));
}

// ---------------------------------------------------------------------------
extern "C" void kernel_launch(void* const* d_in, const int* in_sizes, int n_in,
                              void* d_out, int out_size) {
    const float* x;
    const float* emb;
    if (n_in >= 2 && in_sizes[0] >= in_sizes[1]) {
        x = (const float*)d_in[0]; emb = (const float*)d_in[1];
    } else {
        x = (const float*)d_in[1]; emb = (const float*)d_in[0];
    }

    cudaFuncSetAttribute(vq_main, cudaFuncAttributeMaxDynamicSharedMemorySize, DYNSMEM);

    vq_norm_emb<<<K_ / 8, 256>>>(emb);
    vq_main<<<GRID, TPB, DYNSMEM>>>(x, (float*)d_out, out_size);
    vq_final<<<1, 256>>>((float*)d_out, out_size);
}

// round 7
// speedup vs baseline: 92.6892x; 92.6892x over previous
#include <cuda_runtime.h>
#include <cuda_bf16.h>
#include <math.h>

#define N_   131072
#define D_   64
#define K_   2048
#define RPB  128              // rows per block
#define XSS  132              // padded xs stride (floats)
#define TPB  512
#define GRID (N_ / RPB)       // 1024 blocks

// split: fma-exact codes [0,1280), mma-screened codes [1280,2048)
#define FCH   10              // fma chunks of 128 codes
#define FCPC  128
#define MCH   3               // mma chunks of 256 codes
#define MBASE 1280
#define MCPC  256

#define MARG    0.009f        // bf16 screening margin (validated R4/R5)
#define MARG_FX 299
#define QTH  16               // per-thread queue capacity (mma threads)
#define BPAD 72               // bf16 row pad: 144B rows

typedef unsigned int u32;
typedef unsigned long long u64;

// Device scratch (no allocations allowed)
__device__ __align__(16) float         g_en  [K_ * D_];          // fp32 codebook
__device__ __align__(16) float         g_see [K_];
__device__ __align__(16) float         g_ent [FCH * 64 * FCPC];  // f32 chunk-transposed (codes<1280)
__device__ __align__(16) __nv_bfloat16 g_enbp[(K_-MBASE) * BPAD];// bf16 padded (codes>=1280)
__device__ float g_part[GRID];

// ---- smem byte offsets ----
#define OFF_XS    0           // 33792   xs fp32 [64][132]
#define OFF_FB0   33792       // 32768   fma B buf0 f32 [64][128]
#define OFF_FB1   66560       // 32768   fma B buf1
#define OFF_MA    99328       // 18432   mma A bf16 [128][72h]
#define OFF_MB0   117760      // 36864   mma B buf0 bf16 [256][72h]
#define OFF_MB1   154624      // 36864   mma B buf1
#define OFF_SEES  191488      // 8192    see[2048]
#define OFF_SXX   199680      // 512
#define OFF_RB    200192      // 1024    u64[128] packed (valbits, code)
#define OFF_Q     201216      // 16384   mma queues, interleaved [i][mt]
#define DYNSMEM   217600

// ---------------- helpers ----------------
__device__ __forceinline__ u32 smem_u32(const void* p) {
    u32 a; asm("{ .reg .u64 t; cvta.to.shared.u64 t, %1; cvt.u32.u64 %0, t; }" : "=r"(a) : "l"(p));
    return a;
}
__device__ __forceinline__ void cp16(u32 dst, const void* src) {
    asm volatile("cp.async.cg.shared.global [%0], [%1], 16;" :: "r"(dst), "l"(src) : "memory");
}
__device__ __forceinline__ void cp_commit() { asm volatile("cp.async.commit_group;" ::: "memory"); }
template<int W> __device__ __forceinline__ void cp_wait() {
    asm volatile("cp.async.wait_group %0;" :: "n"(W) : "memory");
}
#define BARG(id) asm volatile("bar.sync %0, 256;" :: "r"(id) : "memory")

__device__ __forceinline__ u64 dup2(float v) {
    u64 r; asm("mov.b64 %0, {%1, %1};" : "=l"(r) : "r"(__float_as_uint(v))); return r;
}
__device__ __forceinline__ u64 fma2(u64 a, u64 b, u64 c) {
    u64 d; asm("fma.rn.f32x2 %0, %1, %2, %3;" : "=l"(d) : "l"(a), "l"(b), "l"(c)); return d;
}
__device__ __forceinline__ u64 add2(u64 a, u64 b) {
    u64 d; asm("add.rn.f32x2 %0, %1, %2;" : "=l"(d) : "l"(a), "l"(b)); return d;
}
__device__ __forceinline__ void unpack2(u64 v, float& lo, float& hi) {
    asm("mov.b64 {%0, %1}, %2;" : "=f"(lo), "=f"(hi) : "l"(v));
}
__device__ __forceinline__ void mma16816(float* c, const u32* a, u32 b0, u32 b1) {
    asm volatile("mma.sync.aligned.m16n8k16.row.col.f32.bf16.bf16.f32 "
        "{%0,%1,%2,%3}, {%4,%5,%6,%7}, {%8,%9}, {%0,%1,%2,%3};"
        : "+f"(c[0]), "+f"(c[1]), "+f"(c[2]), "+f"(c[3])
        : "r"(a[0]), "r"(a[1]), "r"(a[2]), "r"(a[3]), "r"(b0), "r"(b1));
}
__device__ __forceinline__ u32 fix16(float v) {
    float c = fminf(fmaxf(fmaf(v, 32767.f, 32768.f), 0.f), 65535.f);
    return (u32)c;
}
__device__ __forceinline__ u32 keybits(float val) {
    u32 vb = __float_as_uint(val);
    return (vb & 0x80000000u) ? ~vb : (vb | 0x80000000u);    // order-preserving
}
// exact fp32 rescore (identical formula/order everywhere) + atomicMin key
__device__ __noinline__ void exact_rescore(const float* xs, const float* sxx,
                                           u64* rbest, int row, int code) {
    float dot = 0.f;
    const float* er = g_en + code * 64;
    #pragma unroll
    for (int d = 0; d < 64; d++) dot = fmaf(xs[d * XSS + row], er[d], dot);
    float val = fmaf(-2.0f, dot, sxx[row] + g_see[code]);
    u64 key = ((u64)keybits(val) << 32) | (u32)code;
    atomicMin(rbest + row, key);
}

// ---------------------------------------------------------------------------
// Kernel 1: normalize embeddings -> g_en, g_see, g_ent (f32, codes<1280),
// g_enbp (bf16 padded, codes>=1280). One warp per code row.
// ---------------------------------------------------------------------------
__global__ void vq_norm_emb(const float* __restrict__ emb) {
    int w    = (blockIdx.x * blockDim.x + threadIdx.x) >> 5;
    int lane = threadIdx.x & 31;
    if (w >= K_) return;
    float v0 = emb[w * 64 + lane];
    float v1 = emb[w * 64 + lane + 32];
    float s  = v0 * v0 + v1 * v1;
    #pragma unroll
    for (int o = 16; o > 0; o >>= 1) s += __shfl_xor_sync(0xffffffffu, s, o);
    float inv = 1.0f / fmaxf(sqrtf(s), 1e-12f);
    float e0 = v0 * inv, e1 = v1 * inv;
    g_en[w * 64 + lane]      = e0;
    g_en[w * 64 + lane + 32] = e1;
    float t = e0 * e0 + e1 * e1;   // see from ROUNDED values (matches reference)
    #pragma unroll
    for (int o = 16; o > 0; o >>= 1) t += __shfl_xor_sync(0xffffffffu, t, o);
    if (lane == 0) g_see[w] = t;
    if (w < MBASE) {               // fma side: chunk-transposed f32 [ch][d][c]
        int ch = w >> 7, c = w & (FCPC - 1);
        g_ent[(ch * 64 + lane)      * FCPC + c] = e0;
        g_ent[(ch * 64 + lane + 32) * FCPC + c] = e1;
    } else {                        // mma side: bf16 144B-padded rows
        int r = w - MBASE;
        g_enbp[r * BPAD + lane]      = __float2bfloat16(e0);
        g_enbp[r * BPAD + lane + 32] = __float2bfloat16(e1);
    }
}

// ---------------------------------------------------------------------------
// Kernel 2: hybrid — warps 0-7: FFMA2 exact on codes [0,1280);
//                    warps 8-15: bf16 HMMA screen + exact rescore on [1280,2048).
// ---------------------------------------------------------------------------
extern __shared__ char smem_[];

__global__ void __launch_bounds__(TPB, 1)
vq_main(const float* __restrict__ x, float* __restrict__ out, int out_size) {
    char* base = smem_;
    float* xs   = (float*)(base + OFF_XS);
    float* sees = (float*)(base + OFF_SEES);
    float* sxx  = (float*)(base + OFF_SXX);
    u64*   rbest= (u64*)  (base + OFF_RB);

    int tid  = threadIdx.x;
    int warp = tid >> 5, lane = tid & 31;
    int rowbase = blockIdx.x * RPB;
    bool is_fma = (tid < 256);

    if (tid < RPB) rbest[tid] = 0xFFFFFFFFFFFFFFFFull;

    // ---- group-private chunk-0 prefetches ----
    if (is_fma) {
        u32 dst = smem_u32(base + OFF_FB0);
        #pragma unroll
        for (int i = 0; i < 8; i++) {
            int idx = i * 256 + tid;
            cp16(dst + (u32)idx * 16u, (const char*)g_ent + (size_t)idx * 16);
        }
    } else {
        int mt = tid - 256;
        u32 dst = smem_u32(base + OFF_MB0) + (u32)mt * 144u;
        const __nv_bfloat16* src = g_enbp + (size_t)mt * BPAD;
        #pragma unroll
        for (int i = 0; i < 9; i++) cp16(dst + i * 16u, src + i * 8);
    }
    cp_commit();

    // ---- shared prologue ----
    #pragma unroll
    for (int i = 0; i < 16; i++) {
        int e = i * TPB + tid;
        int r = e >> 6, d = e & 63;
        xs[d * XSS + r] = x[(rowbase + r) * 64 + d];
    }
    #pragma unroll
    for (int i = 0; i < 4; i++) sees[i * TPB + tid] = g_see[i * TPB + tid];
    __syncthreads();

    if (tid < RPB) {
        float s = 0.f;
        #pragma unroll
        for (int d = 0; d < 64; d++) { float v = xs[d * XSS + tid]; s += v * v; }
        float inv = 1.0f / fmaxf(sqrtf(s), 1e-12f);
        float s2 = 0.f;
        #pragma unroll
        for (int d = 0; d < 64; d++) {
            float v = xs[d * XSS + tid] * inv;
            xs[d * XSS + tid] = v;
            s2 += v * v;
        }
        sxx[tid] = s2;
    }
    __syncthreads();

    // mma A tile bf16 [row][72h] (built by everyone, used by mma warps)
    #pragma unroll
    for (int i = 0; i < 16; i++) {
        int e = i * TPB + tid;
        int r = e >> 6, d = e & 63;
        *(__nv_bfloat16*)(base + OFF_MA + r * 144 + d * 2) =
            __float2bfloat16(xs[d * XSS + r]);
    }
    __syncthreads();

    if (is_fma) {
        // ================= FFMA2 exact engine (codes 0..1279) =================
        int tx = tid & 15, ty = tid >> 4;
        u64 sxxd[8];
        float minv[8]; int mink[8];
        #pragma unroll
        for (int j = 0; j < 8; j++) {
            sxxd[j] = dup2(sxx[ty * 8 + j]);
            minv[j] = 3.4e38f; mink[j] = 0;
        }
        const u64 M2 = dup2(-2.0f);

        for (int ch = 0; ch < FCH; ch++) {
            if (ch + 1 < FCH) {
                u32 dst = smem_u32(base + (((ch + 1) & 1) ? OFF_FB1 : OFF_FB0));
                const char* src = (const char*)g_ent + (size_t)(ch + 1) * 32768;
                #pragma unroll
                for (int i = 0; i < 8; i++) {
                    int idx = i * 256 + tid;
                    cp16(dst + (u32)idx * 16u, src + (size_t)idx * 16);
                }
                cp_commit();
                cp_wait<1>();
            } else {
                cp_wait<0>();
            }
            BARG(1);

            const u64* eb = (const u64*)(base + ((ch & 1) ? OFF_FB1 : OFF_FB0));
            u64 acc[8][4];
            #pragma unroll
            for (int j = 0; j < 8; j++)
                #pragma unroll
                for (int p = 0; p < 4; p++) acc[j][p] = 0ull;

            #pragma unroll 4
            for (int d = 0; d < 64; d++) {
                float4 a0 = *(const float4*)(xs + d * XSS + ty * 8);
                float4 a1 = *(const float4*)(xs + d * XSS + ty * 8 + 4);
                u64 A[8];
                A[0] = dup2(a0.x); A[1] = dup2(a0.y); A[2] = dup2(a0.z); A[3] = dup2(a0.w);
                A[4] = dup2(a1.x); A[5] = dup2(a1.y); A[6] = dup2(a1.z); A[7] = dup2(a1.w);
                u64 B[4];
                #pragma unroll
                for (int p = 0; p < 4; p++) B[p] = eb[d * 64 + tx + 16 * p];
                #pragma unroll
                for (int j = 0; j < 8; j++)
                    #pragma unroll
                    for (int p = 0; p < 4; p++)
                        acc[j][p] = fma2(A[j], B[p], acc[j][p]);
            }

            const u64* seeb = (const u64*)(sees + ch * FCPC);
            #pragma unroll
            for (int p = 0; p < 4; p++) {
                u64 S = seeb[tx + 16 * p];
                int kb = ch * FCPC + 2 * (tx + 16 * p);
                #pragma unroll
                for (int j = 0; j < 8; j++) {
                    u64 Sp = add2(sxxd[j], S);        // sxx+see, per-lane IEEE
                    u64 v2 = fma2(M2, acc[j][p], Sp); // fma(-2,dot,sxx+see) exact
                    float lo, hi; unpack2(v2, lo, hi);
                    if (lo < minv[j]) { minv[j] = lo; mink[j] = kb; }
                    if (hi < minv[j]) { minv[j] = hi; mink[j] = kb + 1; }
                }
            }
            BARG(1);
        }
        // merge into shared result
        #pragma unroll
        for (int j = 0; j < 8; j++) {
            u64 key = ((u64)keybits(minv[j]) << 32) | (u32)mink[j];
            atomicMin(&rbest[ty * 8 + j], key);
        }
    } else {
        // ============ HMMA bf16 screening engine (codes 1280..2047) ============
        int mt = tid - 256;
        int mwarp = warp - 8;
        int g  = lane >> 2, tq = lane & 3;
        int wy = mwarp & 3;            // 32-row block
        int wx = mwarp >> 2;           // 128-code half of each 256-chunk
        u32* qbuf = (u32*)(base + OFF_Q);

        // A fragments (persist): mapping validated R4/R5
        u32 af[2][4][4];
        #pragma unroll
        for (int amt = 0; amt < 2; amt++) {
            int r0 = wy * 32 + amt * 16 + g;
            #pragma unroll
            for (int k = 0; k < 4; k++) {
                int c0 = (k * 16 + tq * 2) * 2;
                af[amt][k][0] = *(const u32*)(base + OFF_MA + r0 * 144 + c0);
                af[amt][k][1] = *(const u32*)(base + OFF_MA + (r0 + 8) * 144 + c0);
                af[amt][k][2] = *(const u32*)(base + OFF_MA + r0 * 144 + c0 + 16);
                af[amt][k][3] = *(const u32*)(base + OFF_MA + (r0 + 8) * 144 + c0 + 16);
            }
        }

        float rm[4] = { -1e30f, -1e30f, -1e30f, -1e30f };
        int qn = 0;

        for (int ch = 0; ch < MCH; ch++) {
            if (ch + 1 < MCH) {
                u32 dst = smem_u32(base + (((ch + 1) & 1) ? OFF_MB1 : OFF_MB0))
                          + (u32)mt * 144u;
                const __nv_bfloat16* src = g_enbp + (size_t)((ch + 1) * MCPC + mt) * BPAD;
                #pragma unroll
                for (int i = 0; i < 9; i++) cp16(dst + i * 16u, src + i * 8);
                cp_commit();
                cp_wait<1>();
            } else {
                cp_wait<0>();
            }
            BARG(2);

            const char* Bs = base + ((ch & 1) ? OFF_MB1 : OFF_MB0);

            #pragma unroll
            for (int ng = 0; ng < 4; ng++) {
                float acc[2][4][4];
                #pragma unroll
                for (int a2 = 0; a2 < 2; a2++)
                    #pragma unroll
                    for (int nt = 0; nt < 4; nt++)
                        #pragma unroll
                        for (int q = 0; q < 4; q++) acc[a2][nt][q] = 0.f;

                #pragma unroll
                for (int k = 0; k < 4; k++) {
                    #pragma unroll
                    for (int nt = 0; nt < 4; nt++) {
                        int cr = wx * 128 + ng * 32 + nt * 8 + g;
                        int co = k * 32 + tq * 4;
                        u32 b0 = *(const u32*)(Bs + cr * 144 + co);
                        u32 b1 = *(const u32*)(Bs + cr * 144 + co + 16);
                        mma16816(acc[0][nt], af[0][k], b0, b1);
                        mma16816(acc[1][nt], af[1][k], b0, b1);
                    }
                }

                int cbase = MBASE + ch * MCPC + wx * 128 + ng * 32 + tq * 2;

                #pragma unroll
                for (int sid = 0; sid < 4; sid++) {
                    int amt = sid >> 1, qh = (sid & 1) * 2;
                    float gm = fmaxf(fmaxf(acc[amt][0][qh], acc[amt][0][qh + 1]),
                                     fmaxf(acc[amt][1][qh], acc[amt][1][qh + 1]));
                    gm = fmaxf(gm, fmaxf(fmaxf(acc[amt][2][qh], acc[amt][2][qh + 1]),
                                         fmaxf(acc[amt][3][qh], acc[amt][3][qh + 1])));
                    if (gm > rm[sid] - MARG) {          // rare slow path
                        float th = fmaxf(rm[sid], gm) - MARG;
                        #pragma unroll
                        for (int nt = 0; nt < 4; nt++) {
                            #pragma unroll
                            for (int qq = 0; qq < 2; qq++) {
                                float v = acc[amt][nt][qh + qq];
                                if (v > th) {
                                    int code = cbase + nt * 8 + qq;
                                    if (qn >= QTH) {     // purge stale entries
                                        int w2 = 0;
                                        for (int i = 0; i < qn; i++) {
                                            u32 e = qbuf[i * 256 + mt];
                                            int ss = (e >> 12) & 3;
                                            if ((e >> 16) + 4 >= fix16(rm[ss] - MARG))
                                                qbuf[w2++ * 256 + mt] = e;
                                        }
                                        qn = w2;
                                    }
                                    if (qn < QTH) {
                                        qbuf[qn * 256 + mt] =
                                            (fix16(v) << 16) | ((u32)sid << 12) | (u32)(code & 2047);
                                        qn++;
                                    } else {             // guaranteed-correct fallback
                                        exact_rescore(xs, sxx, rbest,
                                            wy * 32 + amt * 16 + (sid & 1) * 8 + g, code);
                                    }
                                }
                            }
                        }
                    }
                    rm[sid] = fmaxf(rm[sid], gm);
                }
            }
            BARG(2);
        }

        // refilter vs final per-thread stream max; exact-rescore survivors
        for (int i = 0; i < qn; i++) {
            u32 e = qbuf[i * 256 + mt];
            int code = e & 2047;
            int sid  = (e >> 12) & 3;
            if ((e >> 16) + MARG_FX >= fix16(rm[sid]))
                exact_rescore(xs, sxx, rbest,
                    wy * 32 + (sid >> 1) * 16 + (sid & 1) * 8 + g, code);
        }
    }
    __syncthreads();

    // ---- per-row final: quantized_st, idx, loss ----
    float lsum = 0.f;
    if (tid < RPB) {
        int bk = (int)(rbest[tid] & 2047u);
        float inv2 = 1.0f / fmaxf(sqrtf(g_see[bk]), 1e-12f);
        const float* erow = g_en + bk * 64;
        #pragma unroll
        for (int d = 0; d < 64; d++) {
            float xnv  = xs[d * XSS + tid];
            float qd   = erow[d] * inv2;
            float diff = qd - xnv;
            lsum += diff * diff;
            xs[d * XSS + tid] = xnv + diff;
        }
        if (out_size >= N_ * D_ + 1 + N_)
            out[N_ * D_ + 1 + rowbase + tid] = (float)bk;
    }
    __syncthreads();

    // coalesced store of quantized_st
    #pragma unroll
    for (int i = 0; i < 16; i++) {
        int e = i * TPB + tid;
        out[rowbase * 64 + e] = xs[(e & 63) * XSS + (e >> 6)];
    }

    // deterministic block loss reduction (reuse sees region)
    float* red = (float*)(base + OFF_SEES);
    if (tid < RPB) red[tid] = lsum;
    __syncthreads();
    for (int s = 64; s > 0; s >>= 1) {
        if (tid < s) red[tid] += red[tid + s];
        __syncthreads();
    }
    if (tid == 0) g_part[blockIdx.x] = red[0];
}

// ---------------------------------------------------------------------------
// Kernel 3: deterministic final loss reduction.
// loss = q_latent + 0.25*e_latent = 1.25 * mean((q - xn)^2)
// ---------------------------------------------------------------------------
__global__ void vq_final(float* __restrict__ out, int out_size) {
    __shared__ float sm[256];
    int tid = threadIdx.x;
    float s = g_part[tid] + g_part[tid + 256] + g_part[tid + 512] + g_part[tid + 768];
    sm[tid] = s;
    __syncthreads();
    for (int st = 128; st > 0; st >>= 1) {
        if (tid < st) sm[tid] += sm[tid + st];
        __syncthreads();
    }
    if (tid == 0 && out_size > N_ * D_)
        out[N_ * D_] = 1.25f * (sm[0] / (float)(N_ * D_));
}

// ---------------------------------------------------------------------------
extern "C" void kernel_launch(void* const* d_in, const int* in_sizes, int n_in,
                              void* d_out, int out_size) {
    const float* x;
    const float* emb;
    if (n_in >= 2 && in_sizes[0] >= in_sizes[1]) {
        x = (const float*)d_in[0]; emb = (const float*)d_in[1];
    } else {
        x = (const float*)d_in[1]; emb = (const float*)d_in[0];
    }

    cudaFuncSetAttribute(vq_main, cudaFuncAttributeMaxDynamicSharedMemorySize, DYNSMEM);

    vq_norm_emb<<<K_ / 8, 256>>>(emb);
    vq_main<<<GRID, TPB, DYNSMEM>>>(x, (float*)d_out, out_size);
    vq_final<<<1, 256>>>((float*)d_out, out_size);
}

// round 8
// speedup vs baseline: 193.1672x; 2.0840x over previous
#include <cuda_runtime.h>
#include <math.h>

// Problem constants (shapes fixed by setup_inputs)
#define N_   131072
#define D_   64
#define K_   2048
#define RPB  128              // rows per block
#define CPC  256              // codes per smem chunk
#define NCH  (K_ / CPC)       // 8 chunks
#define XSS  132              // padded xs stride (floats)
#define TPB  512
#define GRID (N_ / RPB)       // 1024 blocks

typedef unsigned int u32;
typedef unsigned long long u64;

// Device scratch (no allocations allowed)
__device__ __align__(16) float g_en  [K_ * D_];   // normalized codebook [k][d]
__device__ __align__(16) float g_ent [K_ * D_];   // chunk-transposed: [chunk][d][c]
__device__ __align__(16) float g_see [K_];        // sum(en^2) per code
__device__ float g_part[GRID];                    // per-block loss partials

// ---- smem byte offsets ----
#define OFF_XS    0           // 33792   xs fp32 [64][132]
#define OFF_B0    33792       // 65536   B buf0 f32 [64][256]
#define OFF_B1    99328       // 65536   B buf1
#define OFF_SEES  164864      // 8192    see[2048]
#define OFF_SXX   173056      // 512
#define OFF_RK    173568      // 512     int[128] winning code per row
#define DYNSMEM   174080

// ---------------- helpers ----------------
__device__ __forceinline__ u32 smem_u32(const void* p) {
    u32 a; asm("{ .reg .u64 t; cvta.to.shared.u64 t, %1; cvt.u32.u64 %0, t; }" : "=r"(a) : "l"(p));
    return a;
}
__device__ __forceinline__ void cp16(u32 dst, const void* src) {
    asm volatile("cp.async.cg.shared.global [%0], [%1], 16;" :: "r"(dst), "l"(src) : "memory");
}
__device__ __forceinline__ void cp_commit() { asm volatile("cp.async.commit_group;" ::: "memory"); }
template<int W> __device__ __forceinline__ void cp_wait() {
    asm volatile("cp.async.wait_group %0;" :: "n"(W) : "memory");
}
__device__ __forceinline__ u64 dup2(float v) {
    u64 r; asm("mov.b64 %0, {%1, %1};" : "=l"(r) : "r"(__float_as_uint(v))); return r;
}
__device__ __forceinline__ u64 fma2(u64 a, u64 b, u64 c) {
    u64 d; asm("fma.rn.f32x2 %0, %1, %2, %3;" : "=l"(d) : "l"(a), "l"(b), "l"(c)); return d;
}
__device__ __forceinline__ u64 add2(u64 a, u64 b) {
    u64 d; asm("add.rn.f32x2 %0, %1, %2;" : "=l"(d) : "l"(a), "l"(b)); return d;
}
__device__ __forceinline__ void unpack2(u64 v, float& lo, float& hi) {
    asm("mov.b64 {%0, %1}, %2;" : "=f"(lo), "=f"(hi) : "l"(v));
}

// ---------------------------------------------------------------------------
// Kernel 1: normalize embeddings -> row-major + chunk-transposed + see[k].
// One warp per code row (D=64 -> 2 elems/lane).
// ---------------------------------------------------------------------------
__global__ void vq_norm_emb(const float* __restrict__ emb) {
    int w    = (blockIdx.x * blockDim.x + threadIdx.x) >> 5;   // code index
    int lane = threadIdx.x & 31;
    if (w >= K_) return;
    float v0 = emb[w * 64 + lane];
    float v1 = emb[w * 64 + lane + 32];
    float s  = v0 * v0 + v1 * v1;
    #pragma unroll
    for (int o = 16; o > 0; o >>= 1) s += __shfl_xor_sync(0xffffffffu, s, o);
    float inv = 1.0f / fmaxf(sqrtf(s), 1e-12f);
    float e0 = v0 * inv, e1 = v1 * inv;
    g_en[w * 64 + lane]      = e0;
    g_en[w * 64 + lane + 32] = e1;
    float t = e0 * e0 + e1 * e1;   // see from ROUNDED values (matches reference)
    #pragma unroll
    for (int o = 16; o > 0; o >>= 1) t += __shfl_xor_sync(0xffffffffu, t, o);
    if (lane == 0) g_see[w] = t;
    int ch = w >> 8, c = w & (CPC - 1);
    g_ent[(ch * 64 + lane)      * CPC + c] = e0;
    g_ent[(ch * 64 + lane + 32) * CPC + c] = e1;
}

// ---------------------------------------------------------------------------
// Kernel 2: exact FFMA2 argmin, 512 threads (4 warps/SMSP).
// Warp w owns rows 8w..8w+7 exclusively; lane covers code pairs lane+32p.
// A loads are warp-broadcast LDS.128; argmin reduced via shfl within warp.
// ---------------------------------------------------------------------------
extern __shared__ char smem_[];

__global__ void __launch_bounds__(TPB, 1)
vq_main(const float* __restrict__ x, float* __restrict__ out, int out_size) {
    char* base = smem_;
    float* xs   = (float*)(base + OFF_XS);
    float* sees = (float*)(base + OFF_SEES);
    float* sxx  = (float*)(base + OFF_SXX);
    int*   rk   = (int*)  (base + OFF_RK);

    int tid  = threadIdx.x;
    int warp = tid >> 5, lane = tid & 31;
    int rowbase = blockIdx.x * RPB;

    // ---- prefetch B chunk 0 (64KB) ----
    {
        u32 dst = smem_u32(base + OFF_B0);
        #pragma unroll
        for (int i = 0; i < 8; i++) {
            int idx = i * TPB + tid;
            cp16(dst + (u32)idx * 16u, (const char*)g_ent + (size_t)idx * 16);
        }
        cp_commit();
    }

    // ---- load see's (8KB) and x tile (transposed) ----
    #pragma unroll
    for (int i = 0; i < 4; i++) sees[i * TPB + tid] = g_see[i * TPB + tid];
    #pragma unroll
    for (int i = 0; i < 16; i++) {
        int e = i * TPB + tid;
        int r = e >> 6, d = e & 63;
        xs[d * XSS + r] = x[(rowbase + r) * 64 + d];
    }
    __syncthreads();

    // ---- normalize rows (one thread per row); sxx ----
    if (tid < RPB) {
        float s = 0.f;
        #pragma unroll
        for (int d = 0; d < 64; d++) { float v = xs[d * XSS + tid]; s += v * v; }
        float inv = 1.0f / fmaxf(sqrtf(s), 1e-12f);
        float s2 = 0.f;
        #pragma unroll
        for (int d = 0; d < 64; d++) {
            float v = xs[d * XSS + tid] * inv;
            xs[d * XSS + tid] = v;
            s2 += v * v;
        }
        sxx[tid] = s2;
    }
    __syncthreads();

    // per-warp row constants
    u64 sxxd[8];
    #pragma unroll
    for (int j = 0; j < 8; j++) sxxd[j] = dup2(sxx[warp * 8 + j]);

    float minv[8]; int mink[8];
    #pragma unroll
    for (int j = 0; j < 8; j++) { minv[j] = 3.4e38f; mink[j] = 0; }
    const u64 M2 = dup2(-2.0f);

    for (int ch = 0; ch < NCH; ch++) {
        if (ch + 1 < NCH) {
            u32 dst = smem_u32(base + (((ch + 1) & 1) ? OFF_B1 : OFF_B0));
            const char* src = (const char*)g_ent + (size_t)(ch + 1) * 65536;
            #pragma unroll
            for (int i = 0; i < 8; i++) {
                int idx = i * TPB + tid;
                cp16(dst + (u32)idx * 16u, src + (size_t)idx * 16);
            }
            cp_commit();
            cp_wait<1>();     // chunk ch landed
        } else {
            cp_wait<0>();
        }
        __syncthreads();

        const u64* eb = (const u64*)(base + ((ch & 1) ? OFF_B1 : OFF_B0));

        u64 acc[8][4];
        #pragma unroll
        for (int j = 0; j < 8; j++)
            #pragma unroll
            for (int p = 0; p < 4; p++) acc[j][p] = 0ull;

        #pragma unroll 4
        for (int d = 0; d < 64; d++) {
            // A: whole warp reads the same 8 row values -> broadcast LDS
            float4 a0 = *(const float4*)(xs + d * XSS + warp * 8);
            float4 a1 = *(const float4*)(xs + d * XSS + warp * 8 + 4);
            u64 A[8];
            A[0] = dup2(a0.x); A[1] = dup2(a0.y); A[2] = dup2(a0.z); A[3] = dup2(a0.w);
            A[4] = dup2(a1.x); A[5] = dup2(a1.y); A[6] = dup2(a1.z); A[7] = dup2(a1.w);
            u64 B[4];
            #pragma unroll
            for (int p = 0; p < 4; p++) B[p] = eb[d * (CPC / 2) + lane + 32 * p];
            #pragma unroll
            for (int j = 0; j < 8; j++)
                #pragma unroll
                for (int p = 0; p < 4; p++)
                    acc[j][p] = fma2(A[j], B[p], acc[j][p]);
        }

        // exact epilogue: v = fma(-2, dot, sxx + see)  (same formula as R2)
        const u64* seeb = (const u64*)(sees + ch * CPC);
        #pragma unroll
        for (int p = 0; p < 4; p++) {
            u64 S = seeb[lane + 32 * p];
            int kb = ch * CPC + 2 * (lane + 32 * p);
            #pragma unroll
            for (int j = 0; j < 8; j++) {
                u64 Sp = add2(sxxd[j], S);
                u64 v2 = fma2(M2, acc[j][p], Sp);
                float lo, hi; unpack2(v2, lo, hi);
                if (lo < minv[j]) { minv[j] = lo; mink[j] = kb; }
                if (hi < minv[j]) { minv[j] = hi; mink[j] = kb + 1; }
            }
        }
        __syncthreads();     // all reads of this buffer done before next prefetch
    }

    // ---- per-row argmin across the warp's 32 lanes (tie -> smaller code) ----
    #pragma unroll
    for (int j = 0; j < 8; j++) {
        float v = minv[j]; int k = mink[j];
        #pragma unroll
        for (int o = 16; o > 0; o >>= 1) {
            float vo = __shfl_xor_sync(0xffffffffu, v, o);
            int   ko = __shfl_xor_sync(0xffffffffu, k, o);
            if (vo < v || (vo == v && ko < k)) { v = vo; k = ko; }
        }
        if (lane == 0) rk[warp * 8 + j] = k;
    }
    __syncthreads();

    // ---- per-row final: quantized_st, idx, loss ----
    float lsum = 0.f;
    if (tid < RPB) {
        int bk = rk[tid];
        float inv2 = 1.0f / fmaxf(sqrtf(g_see[bk]), 1e-12f);
        const float* erow = g_en + bk * 64;
        #pragma unroll
        for (int d = 0; d < 64; d++) {
            float xnv  = xs[d * XSS + tid];
            float qd   = erow[d] * inv2;
            float diff = qd - xnv;
            lsum += diff * diff;
            xs[d * XSS + tid] = xnv + diff;      // quantized_st
        }
        if (out_size >= N_ * D_ + 1 + N_)
            out[N_ * D_ + 1 + rowbase + tid] = (float)bk;
    }
    __syncthreads();

    // ---- coalesced store of quantized_st ----
    #pragma unroll
    for (int i = 0; i < 16; i++) {
        int e = i * TPB + tid;
        out[rowbase * 64 + e] = xs[(e & 63) * XSS + (e >> 6)];
    }

    // ---- deterministic block loss reduction (reuse sees region) ----
    float* red = (float*)(base + OFF_SEES);
    if (tid < RPB) red[tid] = lsum;
    __syncthreads();
    for (int s = 64; s > 0; s >>= 1) {
        if (tid < s) red[tid] += red[tid + s];
        __syncthreads();
    }
    if (tid == 0) g_part[blockIdx.x] = red[0];
}

// ---------------------------------------------------------------------------
// Kernel 3: deterministic final loss reduction.
// loss = q_latent + 0.25*e_latent = 1.25 * mean((q - xn)^2)
// ---------------------------------------------------------------------------
__global__ void vq_final(float* __restrict__ out, int out_size) {
    __shared__ float sm[256];
    int tid = threadIdx.x;
    float s = g_part[tid] + g_part[tid + 256] + g_part[tid + 512] + g_part[tid + 768];
    sm[tid] = s;
    __syncthreads();
    for (int st = 128; st > 0; st >>= 1) {
        if (tid < st) sm[tid] += sm[tid + st];
        __syncthreads();
    }
    if (tid == 0 && out_size > N_ * D_)
        out[N_ * D_] = 1.25f * (sm[0] / (float)(N_ * D_));
}

// ---------------------------------------------------------------------------
extern "C" void kernel_launch(void* const* d_in, const int* in_sizes, int n_in,
                              void* d_out, int out_size) {
    const float* x;
    const float* emb;
    if (n_in >= 2 && in_sizes[0] >= in_sizes[1]) {
        x = (const float*)d_in[0]; emb = (const float*)d_in[1];
    } else {
        x = (const float*)d_in[1]; emb = (const float*)d_in[0];
    }

    cudaFuncSetAttribute(vq_main, cudaFuncAttributeMaxDynamicSharedMemorySize, DYNSMEM);

    vq_norm_emb<<<K_ / 8, 256>>>(emb);
    vq_main<<<GRID, TPB, DYNSMEM>>>(x, (float*)d_out, out_size);
    vq_final<<<1, 256>>>((float*)d_out, out_size);
}

// round 9
// speedup vs baseline: 201.3183x; 1.0422x over previous
#include <cuda_runtime.h>
#include <math.h>

// Problem constants (shapes fixed by setup_inputs)
#define N_   131072
#define D_   64
#define K_   2048
#define RPB  128              // rows per block
#define CPC  128              // codes per smem chunk
#define NCH  (K_ / CPC)       // 16 chunks
#define XSS  132              // padded xs stride (floats)
#define TPB  256
#define GRID (N_ / RPB)       // 1024 blocks

typedef unsigned int u32;
typedef unsigned long long u64;

// Device scratch (no allocations allowed)
__device__ __align__(16) float g_en  [K_ * D_];   // normalized codebook [k][d]
__device__ __align__(16) float g_ent [K_ * D_];   // chunk-transposed: [chunk][d][c]
__device__ __align__(16) float g_see [K_];        // sum(en^2) per code
__device__ float g_part[GRID];                    // per-block loss partials

// ---- smem byte offsets (total 108544 B -> 2 blocks/SM fit in 228KB) ----
#define OFF_XS    0           // 33792   xs fp32 [64][132]
#define OFF_B0    33792       // 32768   B buf0 f32 [64][128]
#define OFF_B1    66560       // 32768   B buf1
#define OFF_SEES  99328       // 8192    see[2048]
#define OFF_SXX   107520      // 512
#define OFF_RK    108032      // 512     int[128] winning code per row
#define DYNSMEM   108544

// ---------------- helpers ----------------
__device__ __forceinline__ u32 smem_u32(const void* p) {
    u32 a; asm("{ .reg .u64 t; cvta.to.shared.u64 t, %1; cvt.u32.u64 %0, t; }" : "=r"(a) : "l"(p));
    return a;
}
__device__ __forceinline__ void cp16(u32 dst, const void* src) {
    asm volatile("cp.async.cg.shared.global [%0], [%1], 16;" :: "r"(dst), "l"(src) : "memory");
}
__device__ __forceinline__ void cp_commit() { asm volatile("cp.async.commit_group;" ::: "memory"); }
template<int W> __device__ __forceinline__ void cp_wait() {
    asm volatile("cp.async.wait_group %0;" :: "n"(W) : "memory");
}
__device__ __forceinline__ u64 dup2(float v) {
    u64 r; asm("mov.b64 %0, {%1, %1};" : "=l"(r) : "r"(__float_as_uint(v))); return r;
}
__device__ __forceinline__ u64 fma2(u64 a, u64 b, u64 c) {
    u64 d; asm("fma.rn.f32x2 %0, %1, %2, %3;" : "=l"(d) : "l"(a), "l"(b), "l"(c)); return d;
}
__device__ __forceinline__ u64 add2(u64 a, u64 b) {
    u64 d; asm("add.rn.f32x2 %0, %1, %2;" : "=l"(d) : "l"(a), "l"(b)); return d;
}
__device__ __forceinline__ void unpack2(u64 v, float& lo, float& hi) {
    asm("mov.b64 {%0, %1}, %2;" : "=f"(lo), "=f"(hi) : "l"(v));
}

// ---------------------------------------------------------------------------
// Kernel 1: normalize embeddings -> row-major + chunk-transposed + see[k].
// One warp per code row (D=64 -> 2 elems/lane).
// ---------------------------------------------------------------------------
__global__ void vq_norm_emb(const float* __restrict__ emb) {
    int w    = (blockIdx.x * blockDim.x + threadIdx.x) >> 5;   // code index
    int lane = threadIdx.x & 31;
    if (w >= K_) return;
    float v0 = emb[w * 64 + lane];
    float v1 = emb[w * 64 + lane + 32];
    float s  = v0 * v0 + v1 * v1;
    #pragma unroll
    for (int o = 16; o > 0; o >>= 1) s += __shfl_xor_sync(0xffffffffu, s, o);
    float inv = 1.0f / fmaxf(sqrtf(s), 1e-12f);
    float e0 = v0 * inv, e1 = v1 * inv;
    g_en[w * 64 + lane]      = e0;
    g_en[w * 64 + lane + 32] = e1;
    float t = e0 * e0 + e1 * e1;   // see from ROUNDED values (matches reference)
    #pragma unroll
    for (int o = 16; o > 0; o >>= 1) t += __shfl_xor_sync(0xffffffffu, t, o);
    if (lane == 0) g_see[w] = t;
    int ch = w >> 7, c = w & (CPC - 1);
    g_ent[(ch * 64 + lane)      * CPC + c] = e0;
    g_ent[(ch * 64 + lane + 32) * CPC + c] = e1;
}

// ---------------------------------------------------------------------------
// Kernel 2: exact FFMA2 argmin, 256 threads, 2 blocks/SM.
// Thread tile 8 rows (ty) x 8 codes (tx, 4 f32x2 pairs); 16 chunks of 128.
// ---------------------------------------------------------------------------
extern __shared__ char smem_[];

__global__ void __launch_bounds__(TPB, 2)
vq_main(const float* __restrict__ x, float* __restrict__ out, int out_size) {
    char* base = smem_;
    float* xs   = (float*)(base + OFF_XS);
    float* sees = (float*)(base + OFF_SEES);
    float* sxx  = (float*)(base + OFF_SXX);
    int*   rk   = (int*)  (base + OFF_RK);

    int tid  = threadIdx.x;
    int lane = tid & 31;
    int tx   = tid & 15;           // code-pair lane
    int ty   = tid >> 4;           // row group (8 rows)
    int rowbase = blockIdx.x * RPB;

    // ---- prefetch B chunk 0 (32KB) ----
    {
        u32 dst = smem_u32(base + OFF_B0);
        #pragma unroll
        for (int i = 0; i < 8; i++) {
            int idx = i * TPB + tid;
            cp16(dst + (u32)idx * 16u, (const char*)g_ent + (size_t)idx * 16);
        }
        cp_commit();
    }

    // ---- load see's (8KB) and x tile (transposed) ----
    #pragma unroll
    for (int i = 0; i < 8; i++) sees[i * TPB + tid] = g_see[i * TPB + tid];
    #pragma unroll
    for (int i = 0; i < 32; i++) {
        int e = i * TPB + tid;
        int r = e >> 6, d = e & 63;
        xs[d * XSS + r] = x[(rowbase + r) * 64 + d];
    }
    __syncthreads();

    // ---- normalize rows (one thread per row); sxx ----
    if (tid < RPB) {
        float s = 0.f;
        #pragma unroll
        for (int d = 0; d < 64; d++) { float v = xs[d * XSS + tid]; s += v * v; }
        float inv = 1.0f / fmaxf(sqrtf(s), 1e-12f);
        float s2 = 0.f;
        #pragma unroll
        for (int d = 0; d < 64; d++) {
            float v = xs[d * XSS + tid] * inv;
            xs[d * XSS + tid] = v;
            s2 += v * v;
        }
        sxx[tid] = s2;
    }
    __syncthreads();

    float minv[8]; int mink[8];
    #pragma unroll
    for (int j = 0; j < 8; j++) { minv[j] = 3.4e38f; mink[j] = 0; }
    const u64 M2 = dup2(-2.0f);

    for (int ch = 0; ch < NCH; ch++) {
        if (ch + 1 < NCH) {
            u32 dst = smem_u32(base + (((ch + 1) & 1) ? OFF_B1 : OFF_B0));
            const char* src = (const char*)g_ent + (size_t)(ch + 1) * 32768;
            #pragma unroll
            for (int i = 0; i < 8; i++) {
                int idx = i * TPB + tid;
                cp16(dst + (u32)idx * 16u, src + (size_t)idx * 16);
            }
            cp_commit();
            cp_wait<1>();     // chunk ch landed
        } else {
            cp_wait<0>();
        }
        __syncthreads();

        const u64* eb = (const u64*)(base + ((ch & 1) ? OFF_B1 : OFF_B0));

        u64 acc[8][4];
        #pragma unroll
        for (int j = 0; j < 8; j++)
            #pragma unroll
            for (int p = 0; p < 4; p++) acc[j][p] = 0ull;

        #pragma unroll 4
        for (int d = 0; d < 64; d++) {
            float4 a0 = *(const float4*)(xs + d * XSS + ty * 8);
            float4 a1 = *(const float4*)(xs + d * XSS + ty * 8 + 4);
            u64 A[8];
            A[0] = dup2(a0.x); A[1] = dup2(a0.y); A[2] = dup2(a0.z); A[3] = dup2(a0.w);
            A[4] = dup2(a1.x); A[5] = dup2(a1.y); A[6] = dup2(a1.z); A[7] = dup2(a1.w);
            u64 B[4];
            #pragma unroll
            for (int p = 0; p < 4; p++) B[p] = eb[d * (CPC / 2) + tx + 16 * p];
            #pragma unroll
            for (int j = 0; j < 8; j++)
                #pragma unroll
                for (int p = 0; p < 4; p++)
                    acc[j][p] = fma2(A[j], B[p], acc[j][p]);
        }

        // exact epilogue: v = fma(-2, dot, sxx + see)   (same formula as R2)
        const u64* seeb = (const u64*)(sees + ch * CPC);
        #pragma unroll
        for (int p = 0; p < 4; p++) {
            u64 S = seeb[tx + 16 * p];
            int kb = ch * CPC + 2 * (tx + 16 * p);
            #pragma unroll
            for (int j = 0; j < 8; j++) {
                u64 Sp = add2(dup2(sxx[ty * 8 + j]), S);
                u64 v2 = fma2(M2, acc[j][p], Sp);
                float lo, hi; unpack2(v2, lo, hi);
                if (lo < minv[j]) { minv[j] = lo; mink[j] = kb; }
                if (hi < minv[j]) { minv[j] = hi; mink[j] = kb + 1; }
            }
        }
        __syncthreads();     // all reads of this buffer done before next prefetch
    }

    // ---- per-row argmin across the 16 tx threads (same half-warp group) ----
    #pragma unroll
    for (int j = 0; j < 8; j++) {
        float v = minv[j]; int k = mink[j];
        #pragma unroll
        for (int o = 8; o > 0; o >>= 1) {    // xor offsets stay within 16-group
            float vo = __shfl_xor_sync(0xffffffffu, v, o);
            int   ko = __shfl_xor_sync(0xffffffffu, k, o);
            if (vo < v || (vo == v && ko < k)) { v = vo; k = ko; }
        }
        if ((lane & 15) == 0) rk[ty * 8 + j] = k;
    }
    __syncthreads();

    // ---- per-row final: quantized_st, idx, loss ----
    float lsum = 0.f;
    if (tid < RPB) {
        int bk = rk[tid];
        float inv2 = 1.0f / fmaxf(sqrtf(g_see[bk]), 1e-12f);
        const float* erow = g_en + bk * 64;
        #pragma unroll
        for (int d = 0; d < 64; d++) {
            float xnv  = xs[d * XSS + tid];
            float qd   = erow[d] * inv2;
            float diff = qd - xnv;
            lsum += diff * diff;
            xs[d * XSS + tid] = xnv + diff;      // quantized_st
        }
        if (out_size >= N_ * D_ + 1 + N_)
            out[N_ * D_ + 1 + rowbase + tid] = (float)bk;
    }
    __syncthreads();

    // ---- coalesced store of quantized_st ----
    #pragma unroll
    for (int i = 0; i < 32; i++) {
        int e = i * TPB + tid;
        out[rowbase * 64 + e] = xs[(e & 63) * XSS + (e >> 6)];
    }

    // ---- deterministic block loss reduction (reuse sees region) ----
    float* red = (float*)(base + OFF_SEES);
    if (tid < RPB) red[tid] = lsum;
    __syncthreads();
    for (int s = 64; s > 0; s >>= 1) {
        if (tid < s) red[tid] += red[tid + s];
        __syncthreads();
    }
    if (tid == 0) g_part[blockIdx.x] = red[0];
}

// ---------------------------------------------------------------------------
// Kernel 3: deterministic final loss reduction.
// loss = q_latent + 0.25*e_latent = 1.25 * mean((q - xn)^2)
// ---------------------------------------------------------------------------
__global__ void vq_final(float* __restrict__ out, int out_size) {
    __shared__ float sm[256];
    int tid = threadIdx.x;
    float s = g_part[tid] + g_part[tid + 256] + g_part[tid + 512] + g_part[tid + 768];
    sm[tid] = s;
    __syncthreads();
    for (int st = 128; st > 0; st >>= 1) {
        if (tid < st) sm[tid] += sm[tid + st];
        __syncthreads();
    }
    if (tid == 0 && out_size > N_ * D_)
        out[N_ * D_] = 1.25f * (sm[0] / (float)(N_ * D_));
}

// ---------------------------------------------------------------------------
extern "C" void kernel_launch(void* const* d_in, const int* in_sizes, int n_in,
                              void* d_out, int out_size) {
    const float* x;
    const float* emb;
    if (n_in >= 2 && in_sizes[0] >= in_sizes[1]) {
        x = (const float*)d_in[0]; emb = (const float*)d_in[1];
    } else {
        x = (const float*)d_in[1]; emb = (const float*)d_in[0];
    }

    cudaFuncSetAttribute(vq_main, cudaFuncAttributeMaxDynamicSharedMemorySize, DYNSMEM);

    vq_norm_emb<<<K_ / 8, 256>>>(emb);
    vq_main<<<GRID, TPB, DYNSMEM>>>(x, (float*)d_out, out_size);
    vq_final<<<1, 256>>>((float*)d_out, out_size);
}